// round 14
// baseline (speedup 1.0000x reference)
#include <cuda_runtime.h>
#include <cuda_fp16.h>
#include <cfloat>
#include <cstdint>
#include <cstddef>

// Problem dims
#define BATCH   2
#define SLEN    2048
#define HID     2048
#define NHEADS  16
#define HDIM    128
#define H3      6144
#define MROWS   4096
#define SOFTMAX_SCALE 0.08838834764831845f   // 1/sqrt(128)

// ---------------- scratch (static device arrays; no allocations) -------------
__device__ __half g_p[(size_t)MROWS * H3];    // proj (fp16)
__device__ __half g_c[(size_t)MROWS * HID];   // ctx  (fp16)
__device__ __half g_a[(size_t)MROWS * HID];   // hidden fp16
__device__ __half g_b[(size_t)H3 * HID];      // w_pack fp16
__device__ __half g_b2[(size_t)HID * HID];    // w_o fp16

// ===================== small PTX helpers =====================================
__device__ __forceinline__ uint32_t smem_u32(const void* p) {
    uint32_t a;
    asm("{ .reg .u64 t; cvta.to.shared.u64 t, %1; cvt.u32.u64 %0, t; }"
        : "=r"(a) : "l"(p));
    return a;
}
__device__ __forceinline__ void cp_async16(uint32_t saddr, const void* gaddr) {
    asm volatile("cp.async.cg.shared.global [%0], [%1], 16;"
                 :: "r"(saddr), "l"(gaddr) : "memory");
}
__device__ __forceinline__ void cp_commit() {
    asm volatile("cp.async.commit_group;" ::: "memory");
}
template <int N>
__device__ __forceinline__ void cp_wait() {
    asm volatile("cp.async.wait_group %0;" :: "n"(N) : "memory");
}
__device__ __forceinline__ void ldsm_x4(uint32_t* r, uint32_t addr) {
    asm volatile("ldmatrix.sync.aligned.m8n8.x4.shared.b16 {%0,%1,%2,%3}, [%4];"
                 : "=r"(r[0]), "=r"(r[1]), "=r"(r[2]), "=r"(r[3]) : "r"(addr));
}
__device__ __forceinline__ void ldsm_x4_t(uint32_t* r, uint32_t addr) {
    asm volatile("ldmatrix.sync.aligned.m8n8.x4.trans.shared.b16 {%0,%1,%2,%3}, [%4];"
                 : "=r"(r[0]), "=r"(r[1]), "=r"(r[2]), "=r"(r[3]) : "r"(addr));
}
__device__ __forceinline__ void mma16816h(float* c, const uint32_t* a, const uint32_t* b) {
    asm volatile(
        "mma.sync.aligned.m16n8k16.row.col.f32.f16.f16.f32 "
        "{%0,%1,%2,%3}, {%4,%5,%6,%7}, {%8,%9}, {%0,%1,%2,%3};"
        : "+f"(c[0]), "+f"(c[1]), "+f"(c[2]), "+f"(c[3])
        : "r"(a[0]), "r"(a[1]), "r"(a[2]), "r"(a[3]), "r"(b[0]), "r"(b[1]));
}
__device__ __forceinline__ uint32_t pack_h2(float a, float b) {
    __half2 h = __floats2half2_rn(a, b);
    return *(uint32_t*)&h;
}

// ================= fp32 -> fp16 convert (elementwise) ========================
__global__ __launch_bounds__(256)
void cvt_kernel(const float* __restrict__ src, __half* __restrict__ dst, int n)
{
    int i4 = blockIdx.x * blockDim.x + threadIdx.x;
    if (i4 * 4 >= n) return;
    float4 v = *(const float4*)(src + i4 * 4);
    *(uint2*)(dst + i4 * 4) = make_uint2(pack_h2(v.x, v.y), pack_h2(v.z, v.w));
}

// ========== tensor-core GEMM: C[M,N] = A[M,K] * B[N,K]^T (fp16 in) ==========
// OM=0: fp32 C.   OM=1: fp16 C.
// BM=BN=128, BK=64. 256 threads, 8 warps 4(M)x2(N); warp tile 32x64.
// 3-stage cp.async ring, one barrier per chunk, 2 CTAs/SM.
#define GBM 128
#define GBN 128
#define GBK 64
#define MAT_BYTES 16384
#define STAGE_BYTES 32768
#define GT_SMEM (3 * STAGE_BYTES)

template <int OM>
__global__ __launch_bounds__(256, 2)
void gemm_f16(const __half* __restrict__ A, const __half* __restrict__ B,
              float* __restrict__ C, __half* __restrict__ Ch, int N, int K)
{
    extern __shared__ char sm[];
    const uint32_t sbase = smem_u32(sm);
    const int tid  = threadIdx.x;
    const int wid  = tid >> 5;
    const int lane = tid & 31;
    const int bx = blockIdx.x;
    const int by = blockIdx.y;
    const int wm = wid >> 1;
    const int wn = wid & 1;

    const __half* gA = A + (size_t)by * GBM * K;
    const __half* gB = B + (size_t)bx * GBN * K;

    auto prefetch = [&](int c) {
        const uint32_t sst = sbase + (uint32_t)(c % 3) * STAGE_BYTES;
        const int k0 = c * GBK;
#pragma unroll
        for (int i = 0; i < 8; i++) {
            int idx = i * 256 + tid;
            int mat = idx >> 10;
            int within = idx & 1023;
            int kc  = within >> 7;
            int row = within & 127;
            const __half* g = (mat ? gB : gA) + (size_t)row * K + k0 + kc * 8;
            uint32_t s = sst + mat * MAT_BYTES + kc * 2048 + row * 16;
            cp_async16(s, g);
        }
        cp_commit();
    };

    const int subA = lane >> 3;
    const int rowoffA = (lane & 7) + (subA & 1) * 8;
    const int kcselA  = subA >> 1;
    const int rowoffB = (lane & 7) + ((lane >> 4) * 8);
    const int kcselB  = (lane >> 3) & 1;

    float acc[2][8][4];
#pragma unroll
    for (int mt = 0; mt < 2; mt++)
#pragma unroll
        for (int nt = 0; nt < 8; nt++)
#pragma unroll
            for (int q = 0; q < 4; q++) acc[mt][nt][q] = 0.f;

    const int KC = K / GBK;
    prefetch(0);
    prefetch(1);

    for (int c = 0; c < KC; c++) {
        cp_wait<1>();
        __syncthreads();
        if (c + 2 < KC) prefetch(c + 2);

        const uint32_t sst = sbase + (uint32_t)(c % 3) * STAGE_BYTES;
        const uint32_t aBase = sst;
        const uint32_t bBase = sst + MAT_BYTES;

#pragma unroll
        for (int ks = 0; ks < 4; ks++) {
            uint32_t ah[2][4], bh[4][4];
#pragma unroll
            for (int mt = 0; mt < 2; mt++) {
                uint32_t roff = (uint32_t)((ks * 2 + kcselA) * 2048 +
                                           (wm * 32 + mt * 16 + rowoffA) * 16);
                ldsm_x4(ah[mt], aBase + roff);
            }
#pragma unroll
            for (int np = 0; np < 4; np++) {
                uint32_t roff = (uint32_t)((ks * 2 + kcselB) * 2048 +
                                           (wn * 64 + np * 16 + rowoffB) * 16);
                ldsm_x4(bh[np], bBase + roff);
            }
#pragma unroll
            for (int mt = 0; mt < 2; mt++)
#pragma unroll
                for (int np = 0; np < 4; np++)
#pragma unroll
                    for (int j = 0; j < 2; j++)
                        mma16816h(acc[mt][np * 2 + j], ah[mt], &bh[np][j * 2]);
        }
    }

    const int g  = lane >> 2;
    const int t2 = (lane & 3) * 2;
#pragma unroll
    for (int mt = 0; mt < 2; mt++) {
        int row0 = by * GBM + wm * 32 + mt * 16 + g;
#pragma unroll
        for (int nt = 0; nt < 8; nt++) {
            int col = bx * GBN + wn * 64 + nt * 8 + t2;
            if (OM == 0) {
                *(float2*)(C + (size_t)row0 * N + col) =
                    make_float2(acc[mt][nt][0], acc[mt][nt][1]);
                *(float2*)(C + (size_t)(row0 + 8) * N + col) =
                    make_float2(acc[mt][nt][2], acc[mt][nt][3]);
            } else {
                *(uint32_t*)(Ch + (size_t)row0 * N + col) =
                    pack_h2(acc[mt][nt][0], acc[mt][nt][1]);
                *(uint32_t*)(Ch + (size_t)(row0 + 8) * N + col) =
                    pack_h2(acc[mt][nt][2], acc[mt][nt][3]);
            }
        }
    }
}

// ============== tensor-core causal flash attention (fp16 in/out) =============
#define FA_SMEM 49152

__global__ __launch_bounds__(128)
void flash_f16(const __half* __restrict__ p, __half* __restrict__ cc, int b)
{
    extern __shared__ char smc[];
    const uint32_t sb = smem_u32(smc);
    const uint32_t sQ = sb;
    const uint32_t sK = sb + 16384;
    const uint32_t sV = sb + 32768;

    const int tid  = threadIdx.x;
    const int lane = tid & 31;
    const int wm   = tid >> 5;
    const int q0   = (int)(gridDim.x - 1 - blockIdx.x) * 64;
    const int h    = blockIdx.y;
    const int g    = lane >> 2;
    const int t2   = (lane & 3) * 2;

    const size_t rowbase = (size_t)(b * SLEN) * H3 + h * HDIM;

#pragma unroll
    for (int i = 0; i < 8; i++) {
        int item = i * 128 + tid;
        int kcg = item >> 6;
        int row = item & 63;
        cp_async16(sQ + kcg * 1024 + row * 16,
                   p + rowbase + (size_t)(q0 + row) * H3 + kcg * 8);
    }
    cp_commit();
#pragma unroll
    for (int i = 0; i < 8; i++) {
        int item = i * 128 + tid;
        int kcg = item >> 6;
        int row = item & 63;
        cp_async16(sK + kcg * 1024 + row * 16,
                   p + rowbase + (size_t)row * H3 + HID + kcg * 8);
    }
    cp_commit();

    cp_wait<1>();
    __syncthreads();

    const int rowoffA = (lane & 7) + ((lane >> 3) & 1) * 8;
    const int kcselA  = lane >> 4;
    const int rowoffB = (lane & 7) + (lane >> 4) * 8;
    const int kcselB  = (lane >> 3) & 1;

    uint32_t qf[8][4];
#pragma unroll
    for (int k = 0; k < 8; k++) {
        uint32_t roff = (uint32_t)((2 * k + kcselA) * 1024 + (wm * 16 + rowoffA) * 16);
        ldsm_x4(qf[k], sQ + roff);
    }

    float m1 = -FLT_MAX, m2 = -FLT_MAX, l1 = 0.f, l2 = 0.f;
    float o[16][4];
#pragma unroll
    for (int nt = 0; nt < 16; nt++)
#pragma unroll
        for (int q = 0; q < 4; q++) o[nt][q] = 0.f;

    for (int k0 = 0; k0 <= q0; k0 += 64) {
#pragma unroll
        for (int i = 0; i < 8; i++) {
            int item = i * 128 + tid;
            int kcg = item >> 6;
            int row = item & 63;
            cp_async16(sV + kcg * 1024 + row * 16,
                       p + rowbase + (size_t)(k0 + row) * H3 + 2 * HID + kcg * 8);
        }
        cp_commit();

        cp_wait<1>();
        __syncthreads();

        float s[8][4];
#pragma unroll
        for (int nt = 0; nt < 8; nt++)
#pragma unroll
            for (int q = 0; q < 4; q++) s[nt][q] = 0.f;

#pragma unroll
        for (int k = 0; k < 8; k++) {
#pragma unroll
            for (int np = 0; np < 4; np++) {
                uint32_t roff = (uint32_t)((2 * k + kcselB) * 1024 + (np * 16 + rowoffB) * 16);
                uint32_t kf[4];
                ldsm_x4(kf, sK + roff);
#pragma unroll
                for (int j = 0; j < 2; j++)
                    mma16816h(s[np * 2 + j], qf[k], &kf[j * 2]);
            }
        }

#pragma unroll
        for (int nt = 0; nt < 8; nt++)
#pragma unroll
            for (int q = 0; q < 4; q++) s[nt][q] *= SOFTMAX_SCALE;
        if (k0 == q0) {
            int r1 = q0 + wm * 16 + g, r2 = r1 + 8;
#pragma unroll
            for (int nt = 0; nt < 8; nt++) {
                int c0 = k0 + nt * 8 + t2;
                if (c0     > r1) s[nt][0] = -FLT_MAX;
                if (c0 + 1 > r1) s[nt][1] = -FLT_MAX;
                if (c0     > r2) s[nt][2] = -FLT_MAX;
                if (c0 + 1 > r2) s[nt][3] = -FLT_MAX;
            }
        }

        float tm1 = -FLT_MAX, tm2 = -FLT_MAX;
#pragma unroll
        for (int nt = 0; nt < 8; nt++) {
            tm1 = fmaxf(tm1, fmaxf(s[nt][0], s[nt][1]));
            tm2 = fmaxf(tm2, fmaxf(s[nt][2], s[nt][3]));
        }
        tm1 = fmaxf(tm1, __shfl_xor_sync(0xffffffffu, tm1, 1));
        tm1 = fmaxf(tm1, __shfl_xor_sync(0xffffffffu, tm1, 2));
        tm2 = fmaxf(tm2, __shfl_xor_sync(0xffffffffu, tm2, 1));
        tm2 = fmaxf(tm2, __shfl_xor_sync(0xffffffffu, tm2, 2));
        float nm1 = fmaxf(m1, tm1), nm2 = fmaxf(m2, tm2);
        float a1 = __expf(m1 - nm1), a2 = __expf(m2 - nm2);
        m1 = nm1; m2 = nm2;

        float rs1 = 0.f, rs2 = 0.f;
#pragma unroll
        for (int nt = 0; nt < 8; nt++) {
            s[nt][0] = __expf(s[nt][0] - nm1);
            s[nt][1] = __expf(s[nt][1] - nm1);
            s[nt][2] = __expf(s[nt][2] - nm2);
            s[nt][3] = __expf(s[nt][3] - nm2);
            rs1 += s[nt][0] + s[nt][1];
            rs2 += s[nt][2] + s[nt][3];
        }
        rs1 += __shfl_xor_sync(0xffffffffu, rs1, 1);
        rs1 += __shfl_xor_sync(0xffffffffu, rs1, 2);
        rs2 += __shfl_xor_sync(0xffffffffu, rs2, 1);
        rs2 += __shfl_xor_sync(0xffffffffu, rs2, 2);
        l1 = l1 * a1 + rs1;
        l2 = l2 * a2 + rs2;
#pragma unroll
        for (int nt = 0; nt < 16; nt++) {
            o[nt][0] *= a1; o[nt][1] *= a1;
            o[nt][2] *= a2; o[nt][3] *= a2;
        }

        uint32_t p01[8], p23[8];
#pragma unroll
        for (int nt = 0; nt < 8; nt++) {
            p01[nt] = pack_h2(s[nt][0], s[nt][1]);
            p23[nt] = pack_h2(s[nt][2], s[nt][3]);
        }

        cp_wait<0>();
        __syncthreads();
        if (k0 + 64 <= q0) {
#pragma unroll
            for (int i = 0; i < 8; i++) {
                int item = i * 128 + tid;
                int kcg = item >> 6;
                int row = item & 63;
                cp_async16(sK + kcg * 1024 + row * 16,
                           p + rowbase + (size_t)(k0 + 64 + row) * H3 + HID + kcg * 8);
            }
            cp_commit();
        }

#pragma unroll
        for (int kt = 0; kt < 4; kt++) {
            uint32_t pa[4] = {p01[2*kt], p23[2*kt], p01[2*kt+1], p23[2*kt+1]};
#pragma unroll
            for (int np = 0; np < 8; np++) {
                uint32_t roff = (uint32_t)((np * 2 + (lane >> 4)) * 1024 +
                                           (kt * 16 + ((lane >> 3) & 1) * 8 + (lane & 7)) * 16);
                uint32_t vf[4];
                ldsm_x4_t(vf, sV + roff);
#pragma unroll
                for (int j = 0; j < 2; j++)
                    mma16816h(o[np * 2 + j], pa, &vf[j * 2]);
            }
        }
        __syncthreads();
    }

    float inv1 = 1.f / l1, inv2 = 1.f / l2;
    int r1 = q0 + wm * 16 + g;
    size_t base1 = (size_t)(b * SLEN + r1) * HID + h * HDIM;
    size_t base2 = base1 + 8 * HID;
#pragma unroll
    for (int nt = 0; nt < 16; nt++) {
        int col = nt * 8 + t2;
        *(uint32_t*)(cc + base1 + col) = pack_h2(o[nt][0] * inv1, o[nt][1] * inv1);
        *(uint32_t*)(cc + base2 + col) = pack_h2(o[nt][2] * inv2, o[nt][3] * inv2);
    }
}

// ============================ host entry =====================================
extern "C" void kernel_launch(void* const* d_in, const int* in_sizes, int n_in,
                              void* d_out, int out_size)
{
    const float* hidden = (const float*)d_in[0];
    const float* w_pack = (const float*)d_in[2];
    const float* w_o    = (const float*)d_in[3];
    float* out = (float*)d_out;

    __half *p, *c, *a, *bb, *bb2;
    cudaGetSymbolAddress((void**)&p,   g_p);
    cudaGetSymbolAddress((void**)&c,   g_c);
    cudaGetSymbolAddress((void**)&a,   g_a);
    cudaGetSymbolAddress((void**)&bb,  g_b);
    cudaGetSymbolAddress((void**)&bb2, g_b2);

    static bool init_done = false;
    static cudaStream_t s2;
    static cudaEvent_t eq0, eq1, ef0, ef1;
    if (!init_done) {
        cudaFuncSetAttribute(gemm_f16<0>, cudaFuncAttributeMaxDynamicSharedMemorySize, GT_SMEM);
        cudaFuncSetAttribute(gemm_f16<1>, cudaFuncAttributeMaxDynamicSharedMemorySize, GT_SMEM);
        cudaFuncSetAttribute(flash_f16,   cudaFuncAttributeMaxDynamicSharedMemorySize, FA_SMEM);
        cudaStreamCreateWithFlags(&s2, cudaStreamNonBlocking);
        cudaEventCreateWithFlags(&eq0, cudaEventDisableTiming);
        cudaEventCreateWithFlags(&eq1, cudaEventDisableTiming);
        cudaEventCreateWithFlags(&ef0, cudaEventDisableTiming);
        cudaEventCreateWithFlags(&ef1, cudaEventDisableTiming);
        init_done = true;
    }

    const int HALF_ROWS = SLEN;          // 2048 rows per batch

    // 1) converts (stream 0)
    cvt_kernel<<<MROWS * HID / 4 / 256, 256>>>(hidden, a, MROWS * HID);
    cvt_kernel<<<H3 * HID / 4 / 256, 256>>>(w_pack, bb, H3 * HID);
    cvt_kernel<<<HID * HID / 4 / 256, 256>>>(w_o, bb2, HID * HID);

    // 2) QKV projection, split by batch (stream 0)
    gemm_f16<1><<<dim3(H3 / GBN, HALF_ROWS / GBM), 256, GT_SMEM>>>(
        a, bb, nullptr, p, H3, HID);
    cudaEventRecord(eq0, 0);
    gemm_f16<1><<<dim3(H3 / GBN, HALF_ROWS / GBM), 256, GT_SMEM>>>(
        a + (size_t)SLEN * HID, bb, nullptr, p + (size_t)SLEN * H3, H3, HID);
    cudaEventRecord(eq1, 0);

    // 3) flash attention on stream s2, batch by batch
    cudaStreamWaitEvent(s2, eq0, 0);
    flash_f16<<<dim3(SLEN / 64, NHEADS, 1), 128, FA_SMEM, s2>>>(p, c, 0);
    cudaEventRecord(ef0, s2);
    cudaStreamWaitEvent(s2, eq1, 0);
    flash_f16<<<dim3(SLEN / 64, NHEADS, 1), 128, FA_SMEM, s2>>>(p, c, 1);
    cudaEventRecord(ef1, s2);

    // 4) output projection on stream 0, batch by batch (overlaps flash b1)
    cudaStreamWaitEvent(0, ef0, 0);
    gemm_f16<0><<<dim3(HID / GBN, HALF_ROWS / GBM), 256, GT_SMEM>>>(
        c, bb2, out, nullptr, HID, HID);
    cudaStreamWaitEvent(0, ef1, 0);
    gemm_f16<0><<<dim3(HID / GBN, HALF_ROWS / GBM), 256, GT_SMEM>>>(
        c + (size_t)SLEN * HID, bb2, out + (size_t)SLEN * HID, nullptr, HID, HID);
}

// round 15
// speedup vs baseline: 1.0026x; 1.0026x over previous
#include <cuda_runtime.h>
#include <cuda_fp16.h>
#include <cfloat>
#include <cstdint>
#include <cstddef>

// Problem dims
#define BATCH   2
#define SLEN    2048
#define HID     2048
#define NHEADS  16
#define HDIM    128
#define H3      6144
#define MROWS   4096
#define SOFTMAX_SCALE 0.08838834764831845f   // 1/sqrt(128)

// ---------------- scratch (static device arrays; no allocations) -------------
__device__ __half g_p[(size_t)MROWS * H3];    // proj (fp16)
__device__ __half g_c[(size_t)MROWS * HID];   // ctx  (fp16)
__device__ __half g_a[(size_t)MROWS * HID];   // hidden fp16
__device__ __half g_b[(size_t)H3 * HID];      // w_pack fp16
__device__ __half g_b2[(size_t)HID * HID];    // w_o fp16

// ===================== small PTX helpers =====================================
__device__ __forceinline__ uint32_t smem_u32(const void* p) {
    uint32_t a;
    asm("{ .reg .u64 t; cvta.to.shared.u64 t, %1; cvt.u32.u64 %0, t; }"
        : "=r"(a) : "l"(p));
    return a;
}
__device__ __forceinline__ void cp_async16(uint32_t saddr, const void* gaddr) {
    asm volatile("cp.async.cg.shared.global [%0], [%1], 16;"
                 :: "r"(saddr), "l"(gaddr) : "memory");
}
__device__ __forceinline__ void cp_commit() {
    asm volatile("cp.async.commit_group;" ::: "memory");
}
template <int N>
__device__ __forceinline__ void cp_wait() {
    asm volatile("cp.async.wait_group %0;" :: "n"(N) : "memory");
}
__device__ __forceinline__ void ldsm_x4(uint32_t* r, uint32_t addr) {
    asm volatile("ldmatrix.sync.aligned.m8n8.x4.shared.b16 {%0,%1,%2,%3}, [%4];"
                 : "=r"(r[0]), "=r"(r[1]), "=r"(r[2]), "=r"(r[3]) : "r"(addr));
}
__device__ __forceinline__ void ldsm_x4_t(uint32_t* r, uint32_t addr) {
    asm volatile("ldmatrix.sync.aligned.m8n8.x4.trans.shared.b16 {%0,%1,%2,%3}, [%4];"
                 : "=r"(r[0]), "=r"(r[1]), "=r"(r[2]), "=r"(r[3]) : "r"(addr));
}
__device__ __forceinline__ void mma16816h(float* c, const uint32_t* a, const uint32_t* b) {
    asm volatile(
        "mma.sync.aligned.m16n8k16.row.col.f32.f16.f16.f32 "
        "{%0,%1,%2,%3}, {%4,%5,%6,%7}, {%8,%9}, {%0,%1,%2,%3};"
        : "+f"(c[0]), "+f"(c[1]), "+f"(c[2]), "+f"(c[3])
        : "r"(a[0]), "r"(a[1]), "r"(a[2]), "r"(a[3]), "r"(b[0]), "r"(b[1]));
}
__device__ __forceinline__ uint32_t pack_h2(float a, float b) {
    __half2 h = __floats2half2_rn(a, b);
    return *(uint32_t*)&h;
}

// ============ fused fp32 -> fp16 convert for 3 tensors in one launch =========
__global__ __launch_bounds__(256)
void cvt3_kernel(const float* __restrict__ s1, __half* __restrict__ d1, int n1,
                 const float* __restrict__ s2, __half* __restrict__ d2, int n2,
                 const float* __restrict__ s3, __half* __restrict__ d3)
{
    int i = blockIdx.x * blockDim.x + threadIdx.x;   // index in float4 units
    const float* s;
    __half* d;
    int off;
    if (i < n1)            { s = s1; d = d1; off = i; }
    else if (i < n1 + n2)  { s = s2; d = d2; off = i - n1; }
    else                   { s = s3; d = d3; off = i - n1 - n2; }
    float4 v = *(const float4*)(s + (size_t)off * 4);
    *(uint2*)(d + (size_t)off * 4) = make_uint2(pack_h2(v.x, v.y), pack_h2(v.z, v.w));
}

// ========== tensor-core GEMM: C[M,N] = A[M,K] * B[N,K]^T (fp16 in) ==========
// OM=0: fp32 C.   OM=1: fp16 C.
// BM=BN=128, BK=64. 256 threads, 8 warps 4(M)x2(N); warp tile 32x64.
// 3-stage cp.async ring, one barrier per chunk, 2 CTAs/SM.
#define GBM 128
#define GBN 128
#define GBK 64
#define MAT_BYTES 16384
#define STAGE_BYTES 32768
#define GT_SMEM (3 * STAGE_BYTES)

template <int OM>
__global__ __launch_bounds__(256, 2)
void gemm_f16(const __half* __restrict__ A, const __half* __restrict__ B,
              float* __restrict__ C, __half* __restrict__ Ch, int N, int K)
{
    extern __shared__ char sm[];
    const uint32_t sbase = smem_u32(sm);
    const int tid  = threadIdx.x;
    const int wid  = tid >> 5;
    const int lane = tid & 31;
    const int bx = blockIdx.x;
    const int by = blockIdx.y;
    const int wm = wid >> 1;
    const int wn = wid & 1;

    const __half* gA = A + (size_t)by * GBM * K;
    const __half* gB = B + (size_t)bx * GBN * K;

    auto prefetch = [&](int c) {
        const uint32_t sst = sbase + (uint32_t)(c % 3) * STAGE_BYTES;
        const int k0 = c * GBK;
#pragma unroll
        for (int i = 0; i < 8; i++) {
            int idx = i * 256 + tid;
            int mat = idx >> 10;
            int within = idx & 1023;
            int kc  = within >> 7;
            int row = within & 127;
            const __half* g = (mat ? gB : gA) + (size_t)row * K + k0 + kc * 8;
            uint32_t s = sst + mat * MAT_BYTES + kc * 2048 + row * 16;
            cp_async16(s, g);
        }
        cp_commit();
    };

    const int subA = lane >> 3;
    const int rowoffA = (lane & 7) + (subA & 1) * 8;
    const int kcselA  = subA >> 1;
    const int rowoffB = (lane & 7) + ((lane >> 4) * 8);
    const int kcselB  = (lane >> 3) & 1;

    float acc[2][8][4];
#pragma unroll
    for (int mt = 0; mt < 2; mt++)
#pragma unroll
        for (int nt = 0; nt < 8; nt++)
#pragma unroll
            for (int q = 0; q < 4; q++) acc[mt][nt][q] = 0.f;

    const int KC = K / GBK;
    prefetch(0);
    prefetch(1);

    for (int c = 0; c < KC; c++) {
        cp_wait<1>();
        __syncthreads();
        if (c + 2 < KC) prefetch(c + 2);

        const uint32_t sst = sbase + (uint32_t)(c % 3) * STAGE_BYTES;
        const uint32_t aBase = sst;
        const uint32_t bBase = sst + MAT_BYTES;

#pragma unroll
        for (int ks = 0; ks < 4; ks++) {
            uint32_t ah[2][4], bh[4][4];
#pragma unroll
            for (int mt = 0; mt < 2; mt++) {
                uint32_t roff = (uint32_t)((ks * 2 + kcselA) * 2048 +
                                           (wm * 32 + mt * 16 + rowoffA) * 16);
                ldsm_x4(ah[mt], aBase + roff);
            }
#pragma unroll
            for (int np = 0; np < 4; np++) {
                uint32_t roff = (uint32_t)((ks * 2 + kcselB) * 2048 +
                                           (wn * 64 + np * 16 + rowoffB) * 16);
                ldsm_x4(bh[np], bBase + roff);
            }
#pragma unroll
            for (int mt = 0; mt < 2; mt++)
#pragma unroll
                for (int np = 0; np < 4; np++)
#pragma unroll
                    for (int j = 0; j < 2; j++)
                        mma16816h(acc[mt][np * 2 + j], ah[mt], &bh[np][j * 2]);
        }
    }

    const int g  = lane >> 2;
    const int t2 = (lane & 3) * 2;
#pragma unroll
    for (int mt = 0; mt < 2; mt++) {
        int row0 = by * GBM + wm * 32 + mt * 16 + g;
#pragma unroll
        for (int nt = 0; nt < 8; nt++) {
            int col = bx * GBN + wn * 64 + nt * 8 + t2;
            if (OM == 0) {
                *(float2*)(C + (size_t)row0 * N + col) =
                    make_float2(acc[mt][nt][0], acc[mt][nt][1]);
                *(float2*)(C + (size_t)(row0 + 8) * N + col) =
                    make_float2(acc[mt][nt][2], acc[mt][nt][3]);
            } else {
                *(uint32_t*)(Ch + (size_t)row0 * N + col) =
                    pack_h2(acc[mt][nt][0], acc[mt][nt][1]);
                *(uint32_t*)(Ch + (size_t)(row0 + 8) * N + col) =
                    pack_h2(acc[mt][nt][2], acc[mt][nt][3]);
            }
        }
    }
}

// ============== tensor-core causal flash attention (fp16 in/out) =============
#define FA_SMEM 49152

__global__ __launch_bounds__(128)
void flash_f16(const __half* __restrict__ p, __half* __restrict__ cc, int b)
{
    extern __shared__ char smc[];
    const uint32_t sb = smem_u32(smc);
    const uint32_t sQ = sb;
    const uint32_t sK = sb + 16384;
    const uint32_t sV = sb + 32768;

    const int tid  = threadIdx.x;
    const int lane = tid & 31;
    const int wm   = tid >> 5;
    const int q0   = (int)(gridDim.x - 1 - blockIdx.x) * 64;
    const int h    = blockIdx.y;
    const int g    = lane >> 2;
    const int t2   = (lane & 3) * 2;

    const size_t rowbase = (size_t)(b * SLEN) * H3 + h * HDIM;

#pragma unroll
    for (int i = 0; i < 8; i++) {
        int item = i * 128 + tid;
        int kcg = item >> 6;
        int row = item & 63;
        cp_async16(sQ + kcg * 1024 + row * 16,
                   p + rowbase + (size_t)(q0 + row) * H3 + kcg * 8);
    }
    cp_commit();
#pragma unroll
    for (int i = 0; i < 8; i++) {
        int item = i * 128 + tid;
        int kcg = item >> 6;
        int row = item & 63;
        cp_async16(sK + kcg * 1024 + row * 16,
                   p + rowbase + (size_t)row * H3 + HID + kcg * 8);
    }
    cp_commit();

    cp_wait<1>();
    __syncthreads();

    const int rowoffA = (lane & 7) + ((lane >> 3) & 1) * 8;
    const int kcselA  = lane >> 4;
    const int rowoffB = (lane & 7) + (lane >> 4) * 8;
    const int kcselB  = (lane >> 3) & 1;

    uint32_t qf[8][4];
#pragma unroll
    for (int k = 0; k < 8; k++) {
        uint32_t roff = (uint32_t)((2 * k + kcselA) * 1024 + (wm * 16 + rowoffA) * 16);
        ldsm_x4(qf[k], sQ + roff);
    }

    float m1 = -FLT_MAX, m2 = -FLT_MAX, l1 = 0.f, l2 = 0.f;
    float o[16][4];
#pragma unroll
    for (int nt = 0; nt < 16; nt++)
#pragma unroll
        for (int q = 0; q < 4; q++) o[nt][q] = 0.f;

    for (int k0 = 0; k0 <= q0; k0 += 64) {
#pragma unroll
        for (int i = 0; i < 8; i++) {
            int item = i * 128 + tid;
            int kcg = item >> 6;
            int row = item & 63;
            cp_async16(sV + kcg * 1024 + row * 16,
                       p + rowbase + (size_t)(k0 + row) * H3 + 2 * HID + kcg * 8);
        }
        cp_commit();

        cp_wait<1>();
        __syncthreads();

        float s[8][4];
#pragma unroll
        for (int nt = 0; nt < 8; nt++)
#pragma unroll
            for (int q = 0; q < 4; q++) s[nt][q] = 0.f;

#pragma unroll
        for (int k = 0; k < 8; k++) {
#pragma unroll
            for (int np = 0; np < 4; np++) {
                uint32_t roff = (uint32_t)((2 * k + kcselB) * 1024 + (np * 16 + rowoffB) * 16);
                uint32_t kf[4];
                ldsm_x4(kf, sK + roff);
#pragma unroll
                for (int j = 0; j < 2; j++)
                    mma16816h(s[np * 2 + j], qf[k], &kf[j * 2]);
            }
        }

#pragma unroll
        for (int nt = 0; nt < 8; nt++)
#pragma unroll
            for (int q = 0; q < 4; q++) s[nt][q] *= SOFTMAX_SCALE;
        if (k0 == q0) {
            int r1 = q0 + wm * 16 + g, r2 = r1 + 8;
#pragma unroll
            for (int nt = 0; nt < 8; nt++) {
                int c0 = k0 + nt * 8 + t2;
                if (c0     > r1) s[nt][0] = -FLT_MAX;
                if (c0 + 1 > r1) s[nt][1] = -FLT_MAX;
                if (c0     > r2) s[nt][2] = -FLT_MAX;
                if (c0 + 1 > r2) s[nt][3] = -FLT_MAX;
            }
        }

        float tm1 = -FLT_MAX, tm2 = -FLT_MAX;
#pragma unroll
        for (int nt = 0; nt < 8; nt++) {
            tm1 = fmaxf(tm1, fmaxf(s[nt][0], s[nt][1]));
            tm2 = fmaxf(tm2, fmaxf(s[nt][2], s[nt][3]));
        }
        tm1 = fmaxf(tm1, __shfl_xor_sync(0xffffffffu, tm1, 1));
        tm1 = fmaxf(tm1, __shfl_xor_sync(0xffffffffu, tm1, 2));
        tm2 = fmaxf(tm2, __shfl_xor_sync(0xffffffffu, tm2, 1));
        tm2 = fmaxf(tm2, __shfl_xor_sync(0xffffffffu, tm2, 2));
        float nm1 = fmaxf(m1, tm1), nm2 = fmaxf(m2, tm2);
        float a1 = __expf(m1 - nm1), a2 = __expf(m2 - nm2);
        m1 = nm1; m2 = nm2;

        float rs1 = 0.f, rs2 = 0.f;
#pragma unroll
        for (int nt = 0; nt < 8; nt++) {
            s[nt][0] = __expf(s[nt][0] - nm1);
            s[nt][1] = __expf(s[nt][1] - nm1);
            s[nt][2] = __expf(s[nt][2] - nm2);
            s[nt][3] = __expf(s[nt][3] - nm2);
            rs1 += s[nt][0] + s[nt][1];
            rs2 += s[nt][2] + s[nt][3];
        }
        rs1 += __shfl_xor_sync(0xffffffffu, rs1, 1);
        rs1 += __shfl_xor_sync(0xffffffffu, rs1, 2);
        rs2 += __shfl_xor_sync(0xffffffffu, rs2, 1);
        rs2 += __shfl_xor_sync(0xffffffffu, rs2, 2);
        l1 = l1 * a1 + rs1;
        l2 = l2 * a2 + rs2;
#pragma unroll
        for (int nt = 0; nt < 16; nt++) {
            o[nt][0] *= a1; o[nt][1] *= a1;
            o[nt][2] *= a2; o[nt][3] *= a2;
        }

        uint32_t p01[8], p23[8];
#pragma unroll
        for (int nt = 0; nt < 8; nt++) {
            p01[nt] = pack_h2(s[nt][0], s[nt][1]);
            p23[nt] = pack_h2(s[nt][2], s[nt][3]);
        }

        cp_wait<0>();
        __syncthreads();
        if (k0 + 64 <= q0) {
#pragma unroll
            for (int i = 0; i < 8; i++) {
                int item = i * 128 + tid;
                int kcg = item >> 6;
                int row = item & 63;
                cp_async16(sK + kcg * 1024 + row * 16,
                           p + rowbase + (size_t)(k0 + 64 + row) * H3 + HID + kcg * 8);
            }
            cp_commit();
        }

#pragma unroll
        for (int kt = 0; kt < 4; kt++) {
            uint32_t pa[4] = {p01[2*kt], p23[2*kt], p01[2*kt+1], p23[2*kt+1]};
#pragma unroll
            for (int np = 0; np < 8; np++) {
                uint32_t roff = (uint32_t)((np * 2 + (lane >> 4)) * 1024 +
                                           (kt * 16 + ((lane >> 3) & 1) * 8 + (lane & 7)) * 16);
                uint32_t vf[4];
                ldsm_x4_t(vf, sV + roff);
#pragma unroll
                for (int j = 0; j < 2; j++)
                    mma16816h(o[np * 2 + j], pa, &vf[j * 2]);
            }
        }
        __syncthreads();
    }

    float inv1 = 1.f / l1, inv2 = 1.f / l2;
    int r1 = q0 + wm * 16 + g;
    size_t base1 = (size_t)(b * SLEN + r1) * HID + h * HDIM;
    size_t base2 = base1 + 8 * HID;
#pragma unroll
    for (int nt = 0; nt < 16; nt++) {
        int col = nt * 8 + t2;
        *(uint32_t*)(cc + base1 + col) = pack_h2(o[nt][0] * inv1, o[nt][1] * inv1);
        *(uint32_t*)(cc + base2 + col) = pack_h2(o[nt][2] * inv2, o[nt][3] * inv2);
    }
}

// ============================ host entry =====================================
extern "C" void kernel_launch(void* const* d_in, const int* in_sizes, int n_in,
                              void* d_out, int out_size)
{
    const float* hidden = (const float*)d_in[0];
    const float* w_pack = (const float*)d_in[2];
    const float* w_o    = (const float*)d_in[3];
    float* out = (float*)d_out;

    __half *p, *c, *a, *bb, *bb2;
    cudaGetSymbolAddress((void**)&p,   g_p);
    cudaGetSymbolAddress((void**)&c,   g_c);
    cudaGetSymbolAddress((void**)&a,   g_a);
    cudaGetSymbolAddress((void**)&bb,  g_b);
    cudaGetSymbolAddress((void**)&bb2, g_b2);

    static bool init_done = false;
    static cudaStream_t s2;
    static cudaEvent_t eq, ef0, ef1;
    if (!init_done) {
        cudaFuncSetAttribute(gemm_f16<0>, cudaFuncAttributeMaxDynamicSharedMemorySize, GT_SMEM);
        cudaFuncSetAttribute(gemm_f16<1>, cudaFuncAttributeMaxDynamicSharedMemorySize, GT_SMEM);
        cudaFuncSetAttribute(flash_f16,   cudaFuncAttributeMaxDynamicSharedMemorySize, FA_SMEM);
        cudaStreamCreateWithFlags(&s2, cudaStreamNonBlocking);
        cudaEventCreateWithFlags(&eq,  cudaEventDisableTiming);
        cudaEventCreateWithFlags(&ef0, cudaEventDisableTiming);
        cudaEventCreateWithFlags(&ef1, cudaEventDisableTiming);
        init_done = true;
    }

    const int HALF_ROWS = SLEN;              // 2048 rows per batch
    const int n1 = MROWS * HID / 4;          // float4 counts
    const int n2 = H3 * HID / 4;
    const int n3 = HID * HID / 4;

    // 1) fused converts (stream 0)
    cvt3_kernel<<<(n1 + n2 + n3) / 256, 256>>>(hidden, a, n1, w_pack, bb, n2, w_o, bb2);

    // 2) QKV projection: ONE full launch (stream 0)
    gemm_f16<1><<<dim3(H3 / GBN, MROWS / GBM), 256, GT_SMEM>>>(
        a, bb, nullptr, p, H3, HID);
    cudaEventRecord(eq, 0);

    // 3) flash attention on s2, per batch
    cudaStreamWaitEvent(s2, eq, 0);
    flash_f16<<<dim3(SLEN / 64, NHEADS, 1), 128, FA_SMEM, s2>>>(p, c, 0);
    cudaEventRecord(ef0, s2);
    flash_f16<<<dim3(SLEN / 64, NHEADS, 1), 128, FA_SMEM, s2>>>(p, c, 1);
    cudaEventRecord(ef1, s2);

    // 4) output projection on stream 0: b0 overlaps flash b1
    cudaStreamWaitEvent(0, ef0, 0);
    gemm_f16<0><<<dim3(HID / GBN, HALF_ROWS / GBM), 256, GT_SMEM>>>(
        c, bb2, out, nullptr, HID, HID);
    cudaStreamWaitEvent(0, ef1, 0);
    gemm_f16<0><<<dim3(HID / GBN, HALF_ROWS / GBM), 256, GT_SMEM>>>(
        c + (size_t)SLEN * HID, bb2, out + (size_t)SLEN * HID, nullptr, HID, HID);
}

// round 16
// speedup vs baseline: 1.0480x; 1.0453x over previous
#include <cuda_runtime.h>
#include <cuda_fp16.h>
#include <cfloat>
#include <cstdint>
#include <cstddef>

// Problem dims
#define BATCH   2
#define SLEN    2048
#define HID     2048
#define NHEADS  16
#define HDIM    128
#define H3      6144
#define MROWS   4096
#define SOFTMAX_SCALE 0.08838834764831845f   // 1/sqrt(128)

// ---------------- scratch (static device arrays; no allocations) -------------
__device__ __half g_p[(size_t)MROWS * H3];    // proj (fp16)
__device__ __half g_c[(size_t)MROWS * HID];   // ctx  (fp16)
__device__ __half g_a[(size_t)MROWS * HID];   // hidden fp16
__device__ __half g_b[(size_t)H3 * HID];      // w_pack fp16
__device__ __half g_b2[(size_t)HID * HID];    // w_o fp16

// ===================== small PTX helpers =====================================
__device__ __forceinline__ uint32_t smem_u32(const void* p) {
    uint32_t a;
    asm("{ .reg .u64 t; cvta.to.shared.u64 t, %1; cvt.u32.u64 %0, t; }"
        : "=r"(a) : "l"(p));
    return a;
}
__device__ __forceinline__ void cp_async16(uint32_t saddr, const void* gaddr) {
    asm volatile("cp.async.cg.shared.global [%0], [%1], 16;"
                 :: "r"(saddr), "l"(gaddr) : "memory");
}
__device__ __forceinline__ void cp_commit() {
    asm volatile("cp.async.commit_group;" ::: "memory");
}
template <int N>
__device__ __forceinline__ void cp_wait() {
    asm volatile("cp.async.wait_group %0;" :: "n"(N) : "memory");
}
__device__ __forceinline__ void ldsm_x4(uint32_t* r, uint32_t addr) {
    asm volatile("ldmatrix.sync.aligned.m8n8.x4.shared.b16 {%0,%1,%2,%3}, [%4];"
                 : "=r"(r[0]), "=r"(r[1]), "=r"(r[2]), "=r"(r[3]) : "r"(addr));
}
__device__ __forceinline__ void ldsm_x4_t(uint32_t* r, uint32_t addr) {
    asm volatile("ldmatrix.sync.aligned.m8n8.x4.trans.shared.b16 {%0,%1,%2,%3}, [%4];"
                 : "=r"(r[0]), "=r"(r[1]), "=r"(r[2]), "=r"(r[3]) : "r"(addr));
}
__device__ __forceinline__ void mma16816h(float* c, const uint32_t* a, const uint32_t* b) {
    asm volatile(
        "mma.sync.aligned.m16n8k16.row.col.f32.f16.f16.f32 "
        "{%0,%1,%2,%3}, {%4,%5,%6,%7}, {%8,%9}, {%0,%1,%2,%3};"
        : "+f"(c[0]), "+f"(c[1]), "+f"(c[2]), "+f"(c[3])
        : "r"(a[0]), "r"(a[1]), "r"(a[2]), "r"(a[3]), "r"(b[0]), "r"(b[1]));
}
__device__ __forceinline__ uint32_t pack_h2(float a, float b) {
    __half2 h = __floats2half2_rn(a, b);
    return *(uint32_t*)&h;
}

// ============ fused fp32 -> fp16 convert for 3 tensors in one launch =========
__global__ __launch_bounds__(256)
void cvt3_kernel(const float* __restrict__ s1, __half* __restrict__ d1, int n1,
                 const float* __restrict__ s2, __half* __restrict__ d2, int n2,
                 const float* __restrict__ s3, __half* __restrict__ d3)
{
    int i = blockIdx.x * blockDim.x + threadIdx.x;   // index in float4 units
    const float* s;
    __half* d;
    int off;
    if (i < n1)            { s = s1; d = d1; off = i; }
    else if (i < n1 + n2)  { s = s2; d = d2; off = i - n1; }
    else                   { s = s3; d = d3; off = i - n1 - n2; }
    float4 v = *(const float4*)(s + (size_t)off * 4);
    *(uint2*)(d + (size_t)off * 4) = make_uint2(pack_h2(v.x, v.y), pack_h2(v.z, v.w));
}

// ========== tensor-core GEMM: C[M,N] = A[M,K] * B[N,K]^T (fp16 in) ==========
// OM=0: fp32 C.   OM=1: fp16 C.
// BM=BN=128, BK=64. 256 threads, 8 warps 4(M)x2(N); warp tile 32x64.
// 3-stage cp.async ring, one barrier per chunk, 2 CTAs/SM.
#define GBM 128
#define GBN 128
#define GBK 64
#define MAT_BYTES 16384
#define STAGE_BYTES 32768
#define GT_SMEM (3 * STAGE_BYTES)

template <int OM>
__global__ __launch_bounds__(256, 2)
void gemm_f16(const __half* __restrict__ A, const __half* __restrict__ B,
              float* __restrict__ C, __half* __restrict__ Ch, int N, int K)
{
    extern __shared__ char sm[];
    const uint32_t sbase = smem_u32(sm);
    const int tid  = threadIdx.x;
    const int wid  = tid >> 5;
    const int lane = tid & 31;
    const int bx = blockIdx.x;
    const int by = blockIdx.y;
    const int wm = wid >> 1;
    const int wn = wid & 1;

    const __half* gA = A + (size_t)by * GBM * K;
    const __half* gB = B + (size_t)bx * GBN * K;

    auto prefetch = [&](int c) {
        const uint32_t sst = sbase + (uint32_t)(c % 3) * STAGE_BYTES;
        const int k0 = c * GBK;
#pragma unroll
        for (int i = 0; i < 8; i++) {
            int idx = i * 256 + tid;
            int mat = idx >> 10;
            int within = idx & 1023;
            int kc  = within >> 7;
            int row = within & 127;
            const __half* g = (mat ? gB : gA) + (size_t)row * K + k0 + kc * 8;
            uint32_t s = sst + mat * MAT_BYTES + kc * 2048 + row * 16;
            cp_async16(s, g);
        }
        cp_commit();
    };

    const int subA = lane >> 3;
    const int rowoffA = (lane & 7) + (subA & 1) * 8;
    const int kcselA  = subA >> 1;
    const int rowoffB = (lane & 7) + ((lane >> 4) * 8);
    const int kcselB  = (lane >> 3) & 1;

    float acc[2][8][4];
#pragma unroll
    for (int mt = 0; mt < 2; mt++)
#pragma unroll
        for (int nt = 0; nt < 8; nt++)
#pragma unroll
            for (int q = 0; q < 4; q++) acc[mt][nt][q] = 0.f;

    const int KC = K / GBK;
    prefetch(0);
    prefetch(1);

    for (int c = 0; c < KC; c++) {
        cp_wait<1>();
        __syncthreads();
        if (c + 2 < KC) prefetch(c + 2);

        const uint32_t sst = sbase + (uint32_t)(c % 3) * STAGE_BYTES;
        const uint32_t aBase = sst;
        const uint32_t bBase = sst + MAT_BYTES;

#pragma unroll
        for (int ks = 0; ks < 4; ks++) {
            uint32_t ah[2][4], bh[4][4];
#pragma unroll
            for (int mt = 0; mt < 2; mt++) {
                uint32_t roff = (uint32_t)((ks * 2 + kcselA) * 2048 +
                                           (wm * 32 + mt * 16 + rowoffA) * 16);
                ldsm_x4(ah[mt], aBase + roff);
            }
#pragma unroll
            for (int np = 0; np < 4; np++) {
                uint32_t roff = (uint32_t)((ks * 2 + kcselB) * 2048 +
                                           (wn * 64 + np * 16 + rowoffB) * 16);
                ldsm_x4(bh[np], bBase + roff);
            }
#pragma unroll
            for (int mt = 0; mt < 2; mt++)
#pragma unroll
                for (int np = 0; np < 4; np++)
#pragma unroll
                    for (int j = 0; j < 2; j++)
                        mma16816h(acc[mt][np * 2 + j], ah[mt], &bh[np][j * 2]);
        }
    }

    const int g  = lane >> 2;
    const int t2 = (lane & 3) * 2;
#pragma unroll
    for (int mt = 0; mt < 2; mt++) {
        int row0 = by * GBM + wm * 32 + mt * 16 + g;
#pragma unroll
        for (int nt = 0; nt < 8; nt++) {
            int col = bx * GBN + wn * 64 + nt * 8 + t2;
            if (OM == 0) {
                *(float2*)(C + (size_t)row0 * N + col) =
                    make_float2(acc[mt][nt][0], acc[mt][nt][1]);
                *(float2*)(C + (size_t)(row0 + 8) * N + col) =
                    make_float2(acc[mt][nt][2], acc[mt][nt][3]);
            } else {
                *(uint32_t*)(Ch + (size_t)row0 * N + col) =
                    pack_h2(acc[mt][nt][0], acc[mt][nt][1]);
                *(uint32_t*)(Ch + (size_t)(row0 + 8) * N + col) =
                    pack_h2(acc[mt][nt][2], acc[mt][nt][3]);
            }
        }
    }
}

// ============== tensor-core causal flash attention (fp16 in/out) =============
// CTA: 128 q-rows, 8 warps (16 rows each), BN=64 keys/iter.
// smem: Q [kcg16][row128][16B]=32KB, K,V [kcg16][row64][16B]=16KB each -> 64KB
#define FA_SMEM 65536

__global__ __launch_bounds__(256, 1)
void flash_f16(const __half* __restrict__ p, __half* __restrict__ cc)
{
    extern __shared__ char smc[];
    const uint32_t sb = smem_u32(smc);
    const uint32_t sQ = sb;
    const uint32_t sK = sb + 32768;
    const uint32_t sV = sb + 49152;

    const int tid  = threadIdx.x;
    const int lane = tid & 31;
    const int wm   = tid >> 5;                    // 0..7, rows wm*16..
    const int q0   = (int)(gridDim.x - 1 - blockIdx.x) * 128;  // heavy first
    const int h    = blockIdx.y;
    const int b    = blockIdx.z;
    const int g    = lane >> 2;
    const int t2   = (lane & 3) * 2;

    const size_t rowbase = (size_t)(b * SLEN) * H3 + h * HDIM;

    // ---- Q loads (group 0): 2048 items = 16 kcg x 128 rows ----
#pragma unroll
    for (int i = 0; i < 8; i++) {
        int item = i * 256 + tid;
        int kcg = item >> 7;
        int row = item & 127;
        cp_async16(sQ + kcg * 2048 + row * 16,
                   p + rowbase + (size_t)(q0 + row) * H3 + kcg * 8);
    }
    cp_commit();
    // ---- K tile 0 (group 1): 1024 items = 16 kcg x 64 rows ----
#pragma unroll
    for (int i = 0; i < 4; i++) {
        int item = i * 256 + tid;
        int kcg = item >> 6;
        int row = item & 63;
        cp_async16(sK + kcg * 1024 + row * 16,
                   p + rowbase + (size_t)row * H3 + HID + kcg * 8);
    }
    cp_commit();

    cp_wait<1>();
    __syncthreads();

    const int rowoffA = (lane & 7) + ((lane >> 3) & 1) * 8;
    const int kcselA  = lane >> 4;
    const int rowoffB = (lane & 7) + (lane >> 4) * 8;
    const int kcselB  = (lane >> 3) & 1;

    uint32_t qf[8][4];
#pragma unroll
    for (int k = 0; k < 8; k++) {
        uint32_t roff = (uint32_t)((2 * k + kcselA) * 2048 + (wm * 16 + rowoffA) * 16);
        ldsm_x4(qf[k], sQ + roff);
    }

    float m1 = -FLT_MAX, m2 = -FLT_MAX, l1 = 0.f, l2 = 0.f;
    float o[16][4];
#pragma unroll
    for (int nt = 0; nt < 16; nt++)
#pragma unroll
        for (int q = 0; q < 4; q++) o[nt][q] = 0.f;

    const int kend = q0 + 64;      // last k-tile start needed by row q0+127
    for (int k0 = 0; k0 <= kend; k0 += 64) {
        // ---- V loads for this tile ----
#pragma unroll
        for (int i = 0; i < 4; i++) {
            int item = i * 256 + tid;
            int kcg = item >> 6;
            int row = item & 63;
            cp_async16(sV + kcg * 1024 + row * 16,
                       p + rowbase + (size_t)(k0 + row) * H3 + 2 * HID + kcg * 8);
        }
        cp_commit();

        cp_wait<1>();      // K ready
        __syncthreads();

        // ---- S = Q K^T ----
        float s[8][4];
#pragma unroll
        for (int nt = 0; nt < 8; nt++)
#pragma unroll
            for (int q = 0; q < 4; q++) s[nt][q] = 0.f;

#pragma unroll
        for (int k = 0; k < 8; k++) {
#pragma unroll
            for (int np = 0; np < 4; np++) {
                uint32_t roff = (uint32_t)((2 * k + kcselB) * 1024 + (np * 16 + rowoffB) * 16);
                uint32_t kf[4];
                ldsm_x4(kf, sK + roff);
#pragma unroll
                for (int j = 0; j < 2; j++)
                    mma16816h(s[np * 2 + j], qf[k], &kf[j * 2]);
            }
        }

        // ---- scale + causal mask (both diagonal-straddling tiles) ----
#pragma unroll
        for (int nt = 0; nt < 8; nt++)
#pragma unroll
            for (int q = 0; q < 4; q++) s[nt][q] *= SOFTMAX_SCALE;
        if (k0 + 64 > q0) {
            int r1 = q0 + wm * 16 + g, r2 = r1 + 8;
#pragma unroll
            for (int nt = 0; nt < 8; nt++) {
                int c0 = k0 + nt * 8 + t2;
                if (c0     > r1) s[nt][0] = -FLT_MAX;
                if (c0 + 1 > r1) s[nt][1] = -FLT_MAX;
                if (c0     > r2) s[nt][2] = -FLT_MAX;
                if (c0 + 1 > r2) s[nt][3] = -FLT_MAX;
            }
        }

        // ---- online softmax ----
        float tm1 = -FLT_MAX, tm2 = -FLT_MAX;
#pragma unroll
        for (int nt = 0; nt < 8; nt++) {
            tm1 = fmaxf(tm1, fmaxf(s[nt][0], s[nt][1]));
            tm2 = fmaxf(tm2, fmaxf(s[nt][2], s[nt][3]));
        }
        tm1 = fmaxf(tm1, __shfl_xor_sync(0xffffffffu, tm1, 1));
        tm1 = fmaxf(tm1, __shfl_xor_sync(0xffffffffu, tm1, 2));
        tm2 = fmaxf(tm2, __shfl_xor_sync(0xffffffffu, tm2, 1));
        tm2 = fmaxf(tm2, __shfl_xor_sync(0xffffffffu, tm2, 2));
        float nm1 = fmaxf(m1, tm1), nm2 = fmaxf(m2, tm2);
        float a1 = __expf(m1 - nm1), a2 = __expf(m2 - nm2);
        m1 = nm1; m2 = nm2;

        float rs1 = 0.f, rs2 = 0.f;
#pragma unroll
        for (int nt = 0; nt < 8; nt++) {
            s[nt][0] = __expf(s[nt][0] - nm1);
            s[nt][1] = __expf(s[nt][1] - nm1);
            s[nt][2] = __expf(s[nt][2] - nm2);
            s[nt][3] = __expf(s[nt][3] - nm2);
            rs1 += s[nt][0] + s[nt][1];
            rs2 += s[nt][2] + s[nt][3];
        }
        rs1 += __shfl_xor_sync(0xffffffffu, rs1, 1);
        rs1 += __shfl_xor_sync(0xffffffffu, rs1, 2);
        rs2 += __shfl_xor_sync(0xffffffffu, rs2, 1);
        rs2 += __shfl_xor_sync(0xffffffffu, rs2, 2);
        l1 = l1 * a1 + rs1;
        l2 = l2 * a2 + rs2;
#pragma unroll
        for (int nt = 0; nt < 16; nt++) {
            o[nt][0] *= a1; o[nt][1] *= a1;
            o[nt][2] *= a2; o[nt][3] *= a2;
        }

        // ---- P -> fp16 fragments ----
        uint32_t p01[8], p23[8];
#pragma unroll
        for (int nt = 0; nt < 8; nt++) {
            p01[nt] = pack_h2(s[nt][0], s[nt][1]);
            p23[nt] = pack_h2(s[nt][2], s[nt][3]);
        }

        cp_wait<0>();      // V ready
        __syncthreads();
        if (k0 + 64 <= kend) {   // prefetch next K during PV
#pragma unroll
            for (int i = 0; i < 4; i++) {
                int item = i * 256 + tid;
                int kcg = item >> 6;
                int row = item & 63;
                cp_async16(sK + kcg * 1024 + row * 16,
                           p + rowbase + (size_t)(k0 + 64 + row) * H3 + HID + kcg * 8);
            }
            cp_commit();
        }

        // ---- O += P V ----
#pragma unroll
        for (int kt = 0; kt < 4; kt++) {
            uint32_t pa[4] = {p01[2*kt], p23[2*kt], p01[2*kt+1], p23[2*kt+1]};
#pragma unroll
            for (int np = 0; np < 8; np++) {
                uint32_t roff = (uint32_t)((np * 2 + (lane >> 4)) * 1024 +
                                           (kt * 16 + ((lane >> 3) & 1) * 8 + (lane & 7)) * 16);
                uint32_t vf[4];
                ldsm_x4_t(vf, sV + roff);
#pragma unroll
                for (int j = 0; j < 2; j++)
                    mma16816h(o[np * 2 + j], pa, &vf[j * 2]);
            }
        }
        __syncthreads();
    }

    // ---- finalize: write ctx as fp16 ----
    float inv1 = 1.f / l1, inv2 = 1.f / l2;
    int r1 = q0 + wm * 16 + g;
    size_t base1 = (size_t)(b * SLEN + r1) * HID + h * HDIM;
    size_t base2 = base1 + 8 * HID;
#pragma unroll
    for (int nt = 0; nt < 16; nt++) {
        int col = nt * 8 + t2;
        *(uint32_t*)(cc + base1 + col) = pack_h2(o[nt][0] * inv1, o[nt][1] * inv1);
        *(uint32_t*)(cc + base2 + col) = pack_h2(o[nt][2] * inv2, o[nt][3] * inv2);
    }
}

// ============================ host entry =====================================
extern "C" void kernel_launch(void* const* d_in, const int* in_sizes, int n_in,
                              void* d_out, int out_size)
{
    const float* hidden = (const float*)d_in[0];
    const float* w_pack = (const float*)d_in[2];
    const float* w_o    = (const float*)d_in[3];
    float* out = (float*)d_out;

    __half *p, *c, *a, *bb, *bb2;
    cudaGetSymbolAddress((void**)&p,   g_p);
    cudaGetSymbolAddress((void**)&c,   g_c);
    cudaGetSymbolAddress((void**)&a,   g_a);
    cudaGetSymbolAddress((void**)&bb,  g_b);
    cudaGetSymbolAddress((void**)&bb2, g_b2);

    static bool init_done = false;
    if (!init_done) {
        cudaFuncSetAttribute(gemm_f16<0>, cudaFuncAttributeMaxDynamicSharedMemorySize, GT_SMEM);
        cudaFuncSetAttribute(gemm_f16<1>, cudaFuncAttributeMaxDynamicSharedMemorySize, GT_SMEM);
        cudaFuncSetAttribute(flash_f16,   cudaFuncAttributeMaxDynamicSharedMemorySize, FA_SMEM);
        init_done = true;
    }

    const int n1 = MROWS * HID / 4;          // float4 counts
    const int n2 = H3 * HID / 4;
    const int n3 = HID * HID / 4;

    // 1) fused converts
    cvt3_kernel<<<(n1 + n2 + n3) / 256, 256>>>(hidden, a, n1, w_pack, bb, n2, w_o, bb2);

    // 2) QKV projection (one full launch)
    gemm_f16<1><<<dim3(H3 / GBN, MROWS / GBM), 256, GT_SMEM>>>(
        a, bb, nullptr, p, H3, HID);

    // 3) causal flash attention (BM=128, full grid)
    flash_f16<<<dim3(SLEN / 128, NHEADS, BATCH), 256, FA_SMEM>>>(p, c);

    // 4) output projection (one full launch)
    gemm_f16<0><<<dim3(HID / GBN, MROWS / GBM), 256, GT_SMEM>>>(
        c, bb2, out, nullptr, HID, HID);
}